// round 7
// baseline (speedup 1.0000x reference)
#include <cuda_runtime.h>
#include <cuda_bf16.h>
#include <cstdint>

// ======================================================================
// LoRA Linear on GB300 (compute_103 plain target -> NO tcgen05):
//   out = x @ (W + 2*B@A)^T + bias
//   K1: split x (fp32) -> x_hi/x_lo (bf16)
//   K2: W_eff = W + SCALING*B@A, split -> w_hi/w_lo
//   K3: mma.sync m16n8k16 bf16 GEMM, 3-MMA hi/lo split, fp32 accum,
//       cp.async 4-stage pipeline, ldmatrix fragments
// ======================================================================

#define SCALING 2.0f

static constexpr int M_TOTAL = 8192;
static constexpr int N_TOTAL = 4096;
static constexpr int K_TOTAL = 4096;

static constexpr int BM = 128;
static constexpr int BN = 128;
static constexpr int BK = 32;                 // bf16 elems per chunk
static constexpr int NC = K_TOTAL / BK;       // 128 chunks
static constexpr int STAGES = 4;

// smem tile: 128 rows x (32+8 pad) bf16 = 80 B/row
static constexpr int ROW_B   = 80;            // bytes per smem row
static constexpr int TILE_B  = BM * ROW_B;    // 10240 bytes (A and B identical)
static constexpr int STAGE_B = 4 * TILE_B;    // xhi|xlo|whi|wlo = 40960
static constexpr int SMEM_DYN_BYTES = STAGES * STAGE_B;  // 163840

// ---------------- device scratch (allocation-free rule) ----------------
__device__ __nv_bfloat16 g_xhi[(size_t)M_TOTAL * K_TOTAL];
__device__ __nv_bfloat16 g_xlo[(size_t)M_TOTAL * K_TOTAL];
__device__ __nv_bfloat16 g_whi[(size_t)N_TOTAL * K_TOTAL];
__device__ __nv_bfloat16 g_wlo[(size_t)N_TOTAL * K_TOTAL];

// ---------------- PTX helpers (all plain-sm_103 legal) ----------------
__device__ __forceinline__ uint32_t smem_u32(const void* p) {
    uint32_t a;
    asm("{ .reg .u64 t; cvta.to.shared.u64 t, %1; cvt.u32.u64 %0, t; }"
        : "=r"(a) : "l"(p));
    return a;
}

__device__ __forceinline__ void cp_async16(uint32_t dst, const void* src) {
    asm volatile("cp.async.cg.shared.global [%0], [%1], 16;"
                 :: "r"(dst), "l"(src));
}
#define CP_COMMIT() asm volatile("cp.async.commit_group;" ::: "memory")

__device__ __forceinline__ void ldsm4(uint32_t* r, uint32_t addr) {
    asm volatile("ldmatrix.sync.aligned.m8n8.x4.shared.b16 {%0,%1,%2,%3}, [%4];"
                 : "=r"(r[0]), "=r"(r[1]), "=r"(r[2]), "=r"(r[3]) : "r"(addr));
}

__device__ __forceinline__ void mma_bf16(float* d, const uint32_t* a, const uint32_t* b) {
    asm volatile(
        "mma.sync.aligned.m16n8k16.row.col.f32.bf16.bf16.f32 "
        "{%0,%1,%2,%3}, {%4,%5,%6,%7}, {%8,%9}, {%0,%1,%2,%3};"
        : "+f"(d[0]), "+f"(d[1]), "+f"(d[2]), "+f"(d[3])
        : "r"(a[0]), "r"(a[1]), "r"(a[2]), "r"(a[3]), "r"(b[0]), "r"(b[1]));
}

__device__ __forceinline__ void split_bf16(float v, __nv_bfloat16& hi, __nv_bfloat16& lo) {
    hi = __float2bfloat16(v);
    lo = __float2bfloat16(v - __bfloat162float(hi));
}

// ======================================================================
// K1: split x into bf16 hi/lo
// ======================================================================
__global__ __launch_bounds__(256) void prep_x_kernel(const float* __restrict__ x) {
    size_t gid = (size_t)blockIdx.x * blockDim.x + threadIdx.x;  // 1 float4 each
    const float4 v = reinterpret_cast<const float4*>(x)[gid];
    __nv_bfloat16 h0, h1, h2, h3, l0, l1, l2, l3;
    split_bf16(v.x, h0, l0); split_bf16(v.y, h1, l1);
    split_bf16(v.z, h2, l2); split_bf16(v.w, h3, l3);
    uint32_t hi01 = ((uint32_t)__bfloat16_as_ushort(h1) << 16) | __bfloat16_as_ushort(h0);
    uint32_t hi23 = ((uint32_t)__bfloat16_as_ushort(h3) << 16) | __bfloat16_as_ushort(h2);
    uint32_t lo01 = ((uint32_t)__bfloat16_as_ushort(l1) << 16) | __bfloat16_as_ushort(l0);
    uint32_t lo23 = ((uint32_t)__bfloat16_as_ushort(l3) << 16) | __bfloat16_as_ushort(l2);
    reinterpret_cast<uint2*>(g_xhi)[gid] = make_uint2(hi01, hi23);
    reinterpret_cast<uint2*>(g_xlo)[gid] = make_uint2(lo01, lo23);
}

// ======================================================================
// K2: W_eff = W + SCALING * (B @ A), split into bf16 hi/lo
// ======================================================================
__global__ __launch_bounds__(256) void prep_w_kernel(const float* __restrict__ W,
                                                     const float* __restrict__ A,
                                                     const float* __restrict__ B) {
    __shared__ float As[16 * 256];
    __shared__ float Bs[256 * 16];
    const int tid = threadIdx.x;
    const int i0 = blockIdx.x * 256;
    const int o0 = blockIdx.y * 256;

    #pragma unroll
    for (int it = 0; it < 16; ++it) {
        int idx = tid + it * 256;
        int r = idx >> 8, i = idx & 255;
        As[r * 256 + i] = A[r * 4096 + i0 + i];
    }
    #pragma unroll
    for (int it = 0; it < 16; ++it) {
        int idx = tid + it * 256;
        int o = idx >> 4, r = idx & 15;
        Bs[o * 16 + r] = B[(size_t)(o0 + o) * 16 + r];
    }
    __syncthreads();

    const int i = i0 + tid;
    for (int o = 0; o < 256; ++o) {
        float acc = 0.f;
        #pragma unroll
        for (int r = 0; r < 16; ++r)
            acc += Bs[o * 16 + r] * As[r * 256 + tid];
        size_t gi = (size_t)(o0 + o) * 4096 + i;
        float v = W[gi] + SCALING * acc;
        __nv_bfloat16 hi, lo;
        split_bf16(v, hi, lo);
        g_whi[gi] = hi;
        g_wlo[gi] = lo;
    }
}

// ======================================================================
// K3: main GEMM via mma.sync
//   block 256 thr = 8 warps (4 M x 2 N), warp tile 32x64
// ======================================================================
__global__ __launch_bounds__(256, 1) void lora_gemm_kernel(const float* __restrict__ bias,
                                                           float* __restrict__ out) {
    extern __shared__ char dynsmem[];
    const uint32_t smem0 = smem_u32(dynsmem);

    const int tid  = threadIdx.x;
    const int wid  = tid >> 5;
    const int lane = tid & 31;
    const int wm   = wid & 3;          // warp row (M)
    const int wn   = wid >> 2;         // warp col (N)
    const int n0 = blockIdx.x * BN;
    const int m0 = blockIdx.y * BM;

    // ---- loader: one BK chunk (4 tiles) into a stage ----
    auto load_chunk = [&](int stage, int chunk) {
        const uint32_t base = smem0 + stage * STAGE_B;
        const int k0 = chunk * BK;
        #pragma unroll
        for (int it = 0; it < 2; ++it) {
            int idx = it * 256 + tid;          // 0..511
            int row = idx >> 2;                // 0..127
            int c   = idx & 3;                 // 16B chunk in row
            uint32_t off = (uint32_t)(row * ROW_B + c * 16);
            size_t ga = (size_t)(m0 + row) * K_TOTAL + k0 + c * 8;
            size_t gb = (size_t)(n0 + row) * K_TOTAL + k0 + c * 8;
            cp_async16(base + off,              g_xhi + ga);
            cp_async16(base + TILE_B + off,     g_xlo + ga);
            cp_async16(base + 2 * TILE_B + off, g_whi + gb);
            cp_async16(base + 3 * TILE_B + off, g_wlo + gb);
        }
        CP_COMMIT();
    };

    // ---- fragment address bases (byte offsets within a tile) ----
    // A (16x16 tiles): lane -> row = lane%16, kcol16 = (lane/16)*8 elems
    uint32_t aoff[2];
    #pragma unroll
    for (int tm = 0; tm < 2; ++tm)
        aoff[tm] = (uint32_t)((wm * 32 + tm * 16 + (lane & 15)) * ROW_B + (lane >> 4) * 16);
    // B (two 8n x 16k tiles per x4): lane -> nrow = (lane/16)*8 + lane%8,
    //                                        kcol8 = ((lane>>3)&1)*8 elems
    uint32_t boff[4];
    #pragma unroll
    for (int p = 0; p < 4; ++p)
        boff[p] = (uint32_t)((wn * 64 + p * 16 + ((lane >> 4) * 8) + (lane & 7)) * ROW_B
                             + ((lane >> 3) & 1) * 16);

    float acc[2][8][4];
    #pragma unroll
    for (int tm = 0; tm < 2; ++tm)
        #pragma unroll
        for (int tn = 0; tn < 8; ++tn)
            #pragma unroll
            for (int j = 0; j < 4; ++j) acc[tm][tn][j] = 0.f;

    // prologue: 3 stages in flight
    load_chunk(0, 0);
    load_chunk(1, 1);
    load_chunk(2, 2);

    #pragma unroll 1
    for (int c = 0; c < NC; ++c) {
        if (c + 3 <= NC) asm volatile("cp.async.wait_group 2;" ::: "memory");
        else             asm volatile("cp.async.wait_group 0;" ::: "memory");
        __syncthreads();

        const uint32_t sb = smem0 + (c & 3) * STAGE_B;

        #pragma unroll
        for (int kk = 0; kk < 2; ++kk) {
            const uint32_t kb = kk * 32;       // 16 elems * 2B

            uint32_t a[2][2][4];               // [tm][hi/lo][4]
            #pragma unroll
            for (int tm = 0; tm < 2; ++tm) {
                ldsm4(a[tm][0], sb + aoff[tm] + kb);
                ldsm4(a[tm][1], sb + TILE_B + aoff[tm] + kb);
            }

            uint32_t b[8][2][2];               // [tn][hi/lo][2]
            #pragma unroll
            for (int p = 0; p < 4; ++p) {
                uint32_t r[4];
                ldsm4(r, sb + 2 * TILE_B + boff[p] + kb);      // w_hi
                b[2 * p][0][0] = r[0]; b[2 * p][0][1] = r[1];
                b[2 * p + 1][0][0] = r[2]; b[2 * p + 1][0][1] = r[3];
                ldsm4(r, sb + 3 * TILE_B + boff[p] + kb);      // w_lo
                b[2 * p][1][0] = r[0]; b[2 * p][1][1] = r[1];
                b[2 * p + 1][1][0] = r[2]; b[2 * p + 1][1][1] = r[3];
            }

            #pragma unroll
            for (int tm = 0; tm < 2; ++tm)
                #pragma unroll
                for (int tn = 0; tn < 8; ++tn) {
                    mma_bf16(acc[tm][tn], a[tm][0], b[tn][0]);  // hi*hi
                    mma_bf16(acc[tm][tn], a[tm][0], b[tn][1]);  // hi*lo
                    mma_bf16(acc[tm][tn], a[tm][1], b[tn][0]);  // lo*hi
                }
        }

        if (c + 3 < NC) load_chunk((c + 3) & 3, c + 3);
    }

    // ---- epilogue: C frag m16n8 -> gmem with bias ----
    #pragma unroll
    for (int tm = 0; tm < 2; ++tm) {
        const int r0 = m0 + wm * 32 + tm * 16 + (lane >> 2);
        #pragma unroll
        for (int tn = 0; tn < 8; ++tn) {
            const int col = n0 + wn * 64 + tn * 8 + (lane & 3) * 2;
            const float2 bv = *reinterpret_cast<const float2*>(bias + col);
            float2 v0, v1;
            v0.x = acc[tm][tn][0] + bv.x;
            v0.y = acc[tm][tn][1] + bv.y;
            v1.x = acc[tm][tn][2] + bv.x;
            v1.y = acc[tm][tn][3] + bv.y;
            *reinterpret_cast<float2*>(out + (size_t)r0 * N_TOTAL + col) = v0;
            *reinterpret_cast<float2*>(out + (size_t)(r0 + 8) * N_TOTAL + col) = v1;
        }
    }
}

// ======================================================================
// host launcher
// ======================================================================
extern "C" void kernel_launch(void* const* d_in, const int* in_sizes, int n_in,
                              void* d_out, int out_size) {
    const float* x    = (const float*)d_in[0];
    const float* W    = (const float*)d_in[1];
    const float* bias = (const float*)d_in[2];
    const float* A    = (const float*)d_in[3];
    const float* B    = (const float*)d_in[4];
    float* out = (float*)d_out;

    (void)in_sizes; (void)n_in; (void)out_size;

    prep_x_kernel<<<(M_TOTAL * (size_t)K_TOTAL) / (256 * 4), 256>>>(x);
    prep_w_kernel<<<dim3(N_TOTAL / 256, N_TOTAL / 256), 256>>>(W, A, B);

    cudaFuncSetAttribute(lora_gemm_kernel,
                         cudaFuncAttributeMaxDynamicSharedMemorySize, SMEM_DYN_BYTES);
    lora_gemm_kernel<<<dim3(N_TOTAL / BN, M_TOTAL / BM), 256, SMEM_DYN_BYTES>>>(bias, out);
}